// round 1
// baseline (speedup 1.0000x reference)
#include <cuda_runtime.h>
#include <cuda_bf16.h>
#include <cstdint>

// ---------------- problem constants ----------------
#define N_MI   100000
#define N_DI   50000
#define N_E    500000
#define N_L    200000
#define F_MI_C 256
#define F_DI_C 128
#define H_C    128

// ---------------- device scratch (sanctioned: __device__ globals) ----------------
__device__ float g_hA_mi[(size_t)N_MI * 256];
__device__ float g_hB_mi[(size_t)N_MI * 256];
__device__ float g_hA_di[(size_t)N_DI * 256];
__device__ float g_hB_di[(size_t)N_DI * 256];
__device__ float g_mean_mi[(size_t)N_MI * 256];
__device__ float g_mean_di[(size_t)N_DI * 256];

__device__ int g_rowptr_di[N_DI + 1];
__device__ int g_rowptr_mi[N_MI + 1];
__device__ int g_col_di[N_E];   // for each di node: list of mi src ids
__device__ int g_col_mi[N_E];   // for each mi node: list of di dst ids
__device__ int g_cnt_di[N_DI];
__device__ int g_cnt_mi[N_MI];

// ---------------- CSR build ----------------
__global__ void count_edges(const int* __restrict__ src, const int* __restrict__ dst, int e) {
    int i = blockIdx.x * blockDim.x + threadIdx.x;
    if (i < e) {
        atomicAdd(&g_cnt_mi[src[i]], 1);
        atomicAdd(&g_cnt_di[dst[i]], 1);
    }
}

// block 0 scans cnt_di -> rowptr_di, block 1 scans cnt_mi -> rowptr_mi
__global__ void scan2() {
    const int* cnt = blockIdx.x ? g_cnt_mi : g_cnt_di;
    int* rowptr    = blockIdx.x ? g_rowptr_mi : g_rowptr_di;
    int n          = blockIdx.x ? N_MI : N_DI;

    __shared__ int warpsum[32];
    __shared__ int s_running;
    int tid = threadIdx.x, lane = tid & 31, wid = tid >> 5;
    if (tid == 0) s_running = 0;
    __syncthreads();

    for (int base = 0; base < n; base += 1024) {
        int i = base + tid;
        int v = (i < n) ? cnt[i] : 0;
        int x = v;
        #pragma unroll
        for (int off = 1; off < 32; off <<= 1) {
            int t = __shfl_up_sync(0xffffffffu, x, off);
            if (lane >= off) x += t;
        }
        if (lane == 31) warpsum[wid] = x;
        __syncthreads();
        if (wid == 0) {
            int w = warpsum[lane];
            #pragma unroll
            for (int off = 1; off < 32; off <<= 1) {
                int t = __shfl_up_sync(0xffffffffu, w, off);
                if (lane >= off) w += t;
            }
            warpsum[lane] = w;
        }
        __syncthreads();
        int incl = x + (wid ? warpsum[wid - 1] : 0);
        int run = s_running;
        if (i < n) rowptr[i] = run + incl - v;
        __syncthreads();
        if (tid == 1023) s_running = run + warpsum[31];
        __syncthreads();
    }
    if (threadIdx.x == 0) rowptr[n] = s_running;
}

__global__ void fill_edges(const int* __restrict__ src, const int* __restrict__ dst, int e) {
    int i = blockIdx.x * blockDim.x + threadIdx.x;
    if (i < e) {
        int s = src[i], d = dst[i];
        int pd = g_rowptr_di[d] + atomicAdd(&g_cnt_di[d], 1);
        g_col_di[pd] = s;
        int pm = g_rowptr_mi[s] + atomicAdd(&g_cnt_mi[s], 1);
        g_col_mi[pm] = d;
    }
}

// ---------------- mean aggregation: one warp per destination row ----------------
template <int D>
__global__ void agg_mean(const float* __restrict__ x, const int* __restrict__ rowptr,
                         const int* __restrict__ col, float* __restrict__ out, int n) {
    int warp = (blockIdx.x * blockDim.x + threadIdx.x) >> 5;
    int lane = threadIdx.x & 31;
    if (warp >= n) return;
    int s = rowptr[warp], e = rowptr[warp + 1];
    float acc[D / 32];
    #pragma unroll
    for (int j = 0; j < D / 32; ++j) acc[j] = 0.f;
    for (int i = s; i < e; ++i) {
        int srcid = col[i];
        const float* xr = x + (size_t)srcid * D;
        #pragma unroll
        for (int j = 0; j < D / 32; ++j) acc[j] += __ldg(xr + lane + 32 * j);
    }
    float inv = 1.f / fmaxf((float)(e - s), 1.f);
    float* o = out + (size_t)warp * D;
    #pragma unroll
    for (int j = 0; j < D / 32; ++j) o[lane + 32 * j] = acc[j] * inv;
}

// ---------------- fused SGEMM: C = A0@B0^T (+ A1@B1^T) + bias (+ addend), optional relu ----
// A: [M,K] row-major, B: [N,K] row-major (so C = A @ B^T), C: [M,N]
#define BM 128
#define BN 64
#define BKT 16

__global__ void __launch_bounds__(256, 2) sage_gemm(
    const float* __restrict__ A0, const float* __restrict__ B0,
    const float* __restrict__ A1, const float* __restrict__ B1,
    const float* __restrict__ bias, const float* __restrict__ addend,
    float* __restrict__ C, int M, int N, int K, int relu) {

    __shared__ float As[BKT][BM];
    __shared__ float Bs[BKT][BN];

    int tid = threadIdx.x;
    int m0 = blockIdx.y * BM;
    int n0 = blockIdx.x * BN;
    int tm = (tid / 16) * 8;   // 0..120
    int tn = (tid % 16) * 4;   // 0..60

    float acc[8][4];
    #pragma unroll
    for (int i = 0; i < 8; ++i)
        #pragma unroll
        for (int j = 0; j < 4; ++j) acc[i][j] = 0.f;

    #pragma unroll 1
    for (int p = 0; p < 2; ++p) {
        const float* A = p ? A1 : A0;
        const float* B = p ? B1 : B0;
        if (A == nullptr) continue;
        #pragma unroll 1
        for (int k0 = 0; k0 < K; k0 += BKT) {
            // A tile: 128x16 = 512 float4, 2 per thread
            #pragma unroll
            for (int it = 0; it < 2; ++it) {
                int idx = tid * 2 + it;
                int r = idx >> 2;
                int c4 = (idx & 3) * 4;
                float4 v = make_float4(0.f, 0.f, 0.f, 0.f);
                if (m0 + r < M) v = *(const float4*)(A + (size_t)(m0 + r) * K + k0 + c4);
                As[c4 + 0][r] = v.x; As[c4 + 1][r] = v.y;
                As[c4 + 2][r] = v.z; As[c4 + 3][r] = v.w;
            }
            // B tile: 64x16 = 256 float4, 1 per thread (N always multiple of 64)
            {
                int r = tid >> 2;
                int c4 = (tid & 3) * 4;
                float4 v = *(const float4*)(B + (size_t)(n0 + r) * K + k0 + c4);
                Bs[c4 + 0][r] = v.x; Bs[c4 + 1][r] = v.y;
                Bs[c4 + 2][r] = v.z; Bs[c4 + 3][r] = v.w;
            }
            __syncthreads();
            #pragma unroll
            for (int k = 0; k < BKT; ++k) {
                float ra[8], rb[4];
                #pragma unroll
                for (int i = 0; i < 8; ++i) ra[i] = As[k][tm + i];
                #pragma unroll
                for (int j = 0; j < 4; ++j) rb[j] = Bs[k][tn + j];
                #pragma unroll
                for (int i = 0; i < 8; ++i)
                    #pragma unroll
                    for (int j = 0; j < 4; ++j) acc[i][j] += ra[i] * rb[j];
            }
            __syncthreads();
        }
    }

    #pragma unroll
    for (int i = 0; i < 8; ++i) {
        int row = m0 + tm + i;
        if (row < M) {
            #pragma unroll
            for (int j = 0; j < 4; ++j) {
                int colg = n0 + tn + j;
                float v = acc[i][j] + bias[colg];
                if (addend) v += addend[(size_t)row * N + colg];
                if (relu) v = fmaxf(v, 0.f);
                C[(size_t)row * N + colg] = v;
            }
        }
    }
}

// ---------------- classifier: out[l] = dot64(h_mi[ls[l]], h_di[ld[l]]) ----------------
__global__ void dot64(const float* __restrict__ hmi, const float* __restrict__ hdi,
                      const int* __restrict__ lsrc, const int* __restrict__ ldst,
                      float* __restrict__ out, int L) {
    int warp = (blockIdx.x * blockDim.x + threadIdx.x) >> 5;
    int lane = threadIdx.x & 31;
    if (warp >= L) return;
    const float2* a = (const float2*)(hmi + (size_t)lsrc[warp] * 64);
    const float2* b = (const float2*)(hdi + (size_t)ldst[warp] * 64);
    float2 av = a[lane], bv = b[lane];
    float p = av.x * bv.x + av.y * bv.y;
    #pragma unroll
    for (int off = 16; off; off >>= 1) p += __shfl_down_sync(0xffffffffu, p, off);
    if (lane == 0) out[warp] = p;
}

// ---------------- host orchestration ----------------
static inline dim3 gemm_grid(int M, int N) { return dim3(N / BN, (M + BM - 1) / BM); }

extern "C" void kernel_launch(void* const* d_in, const int* in_sizes, int n_in,
                              void* d_out, int out_size) {
    const float* x_mi   = (const float*)d_in[0];
    const float* x_di   = (const float*)d_in[1];
    const float* W_mi   = (const float*)d_in[2];
    const float* b_mi   = (const float*)d_in[3];
    const float* W_di   = (const float*)d_in[4];
    const float* b_di   = (const float*)d_in[5];
    const float* emb_mi = (const float*)d_in[6];
    const float* emb_di = (const float*)d_in[7];
    const float *Wl[3][2], *bl[3][2], *Wr[3][2];   // [layer][0=md,1=dm]
    for (int i = 0; i < 3; ++i)
        for (int r = 0; r < 2; ++r) {
            int base = 8 + i * 6 + r * 3;
            Wl[i][r] = (const float*)d_in[base];
            bl[i][r] = (const float*)d_in[base + 1];
            Wr[i][r] = (const float*)d_in[base + 2];
        }
    const int* edge_src  = (const int*)d_in[26];
    const int* edge_dst  = (const int*)d_in[27];
    const int* label_src = (const int*)d_in[28];
    const int* label_dst = (const int*)d_in[29];
    float* out = (float*)d_out;

    float *hA_mi, *hB_mi, *hA_di, *hB_di, *mean_mi, *mean_di;
    int *rp_di, *rp_mi, *col_di, *col_mi, *cnt_di, *cnt_mi;
    cudaGetSymbolAddress((void**)&hA_mi, g_hA_mi);
    cudaGetSymbolAddress((void**)&hB_mi, g_hB_mi);
    cudaGetSymbolAddress((void**)&hA_di, g_hA_di);
    cudaGetSymbolAddress((void**)&hB_di, g_hB_di);
    cudaGetSymbolAddress((void**)&mean_mi, g_mean_mi);
    cudaGetSymbolAddress((void**)&mean_di, g_mean_di);
    cudaGetSymbolAddress((void**)&rp_di, g_rowptr_di);
    cudaGetSymbolAddress((void**)&rp_mi, g_rowptr_mi);
    cudaGetSymbolAddress((void**)&col_di, g_col_di);
    cudaGetSymbolAddress((void**)&col_mi, g_col_mi);
    cudaGetSymbolAddress((void**)&cnt_di, g_cnt_di);
    cudaGetSymbolAddress((void**)&cnt_mi, g_cnt_mi);

    const int EB = (N_E + 255) / 256;

    // ---- CSR build (reused by all 3 layers) ----
    cudaMemsetAsync(cnt_di, 0, N_DI * sizeof(int));
    cudaMemsetAsync(cnt_mi, 0, N_MI * sizeof(int));
    count_edges<<<EB, 256>>>(edge_src, edge_dst, N_E);
    scan2<<<2, 1024>>>();
    cudaMemsetAsync(cnt_di, 0, N_DI * sizeof(int));
    cudaMemsetAsync(cnt_mi, 0, N_MI * sizeof(int));
    fill_edges<<<EB, 256>>>(edge_src, edge_dst, N_E);

    // ---- input projections: h = x @ W^T + b + emb ----
    sage_gemm<<<gemm_grid(N_MI, H_C), 256>>>(x_mi, W_mi, nullptr, nullptr,
                                             b_mi, emb_mi, hA_mi, N_MI, H_C, F_MI_C, 0);
    sage_gemm<<<gemm_grid(N_DI, H_C), 256>>>(x_di, W_di, nullptr, nullptr,
                                             b_di, emb_di, hA_di, N_DI, H_C, F_DI_C, 0);

    const int AG_DI = (N_DI + 7) / 8;   // 8 warps/block
    const int AG_MI = (N_MI + 7) / 8;

    // ---- Layer 1: in 128 -> out 256, relu ----
    agg_mean<128><<<AG_DI, 256>>>(hA_mi, rp_di, col_di, mean_di, N_DI);
    agg_mean<128><<<AG_MI, 256>>>(hA_di, rp_mi, col_mi, mean_mi, N_MI);
    sage_gemm<<<gemm_grid(N_DI, 256), 256>>>(mean_di, Wl[0][0], hA_di, Wr[0][0],
                                             bl[0][0], nullptr, hB_di, N_DI, 256, 128, 1);
    sage_gemm<<<gemm_grid(N_MI, 256), 256>>>(mean_mi, Wl[0][1], hA_mi, Wr[0][1],
                                             bl[0][1], nullptr, hB_mi, N_MI, 256, 128, 1);

    // ---- Layer 2: in 256 -> out 128, relu ----
    agg_mean<256><<<AG_DI, 256>>>(hB_mi, rp_di, col_di, mean_di, N_DI);
    agg_mean<256><<<AG_MI, 256>>>(hB_di, rp_mi, col_mi, mean_mi, N_MI);
    sage_gemm<<<gemm_grid(N_DI, 128), 256>>>(mean_di, Wl[1][0], hB_di, Wr[1][0],
                                             bl[1][0], nullptr, hA_di, N_DI, 128, 256, 1);
    sage_gemm<<<gemm_grid(N_MI, 128), 256>>>(mean_mi, Wl[1][1], hB_mi, Wr[1][1],
                                             bl[1][1], nullptr, hA_mi, N_MI, 128, 256, 1);

    // ---- Layer 3: in 128 -> out 64, no relu ----
    agg_mean<128><<<AG_DI, 256>>>(hA_mi, rp_di, col_di, mean_di, N_DI);
    agg_mean<128><<<AG_MI, 256>>>(hA_di, rp_mi, col_mi, mean_mi, N_MI);
    sage_gemm<<<gemm_grid(N_DI, 64), 256>>>(mean_di, Wl[2][0], hA_di, Wr[2][0],
                                            bl[2][0], nullptr, hB_di, N_DI, 64, 128, 0);
    sage_gemm<<<gemm_grid(N_MI, 64), 256>>>(mean_mi, Wl[2][1], hA_mi, Wr[2][1],
                                            bl[2][1], nullptr, hB_mi, N_MI, 64, 128, 0);

    // ---- classifier ----
    dot64<<<(N_L + 7) / 8, 256>>>(hB_mi, hB_di, label_src, label_dst, out, N_L);
}

// round 2
// speedup vs baseline: 2.1634x; 2.1634x over previous
#include <cuda_runtime.h>
#include <cuda_bf16.h>
#include <cstdint>

// ---------------- problem constants ----------------
#define N_MI   100000
#define N_DI   50000
#define N_E    500000
#define N_L    200000
#define F_MI_C 256
#define F_DI_C 128
#define H_C    128

// ---------------- device scratch ----------------
__device__ float g_hA_mi[(size_t)N_MI * 256];
__device__ float g_hB_mi[(size_t)N_MI * 256];
__device__ float g_hA_di[(size_t)N_DI * 256];
__device__ float g_hB_di[(size_t)N_DI * 256];
__device__ float g_mean_mi[(size_t)N_MI * 256];
__device__ float g_mean_di[(size_t)N_DI * 256];

__device__ int g_rowptr_di[N_DI + 1];
__device__ int g_rowptr_mi[N_MI + 1];
__device__ int g_col_di[N_E];
__device__ int g_col_mi[N_E];
__device__ int g_cnt_di[N_DI];
__device__ int g_cnt_mi[N_MI];

// ---------------- CSR build ----------------
__global__ void count_edges(const int* __restrict__ src, const int* __restrict__ dst, int e) {
    int i = blockIdx.x * blockDim.x + threadIdx.x;
    if (i < e) {
        atomicAdd(&g_cnt_mi[src[i]], 1);
        atomicAdd(&g_cnt_di[dst[i]], 1);
    }
}

__global__ void scan2() {
    const int* cnt = blockIdx.x ? g_cnt_mi : g_cnt_di;
    int* rowptr    = blockIdx.x ? g_rowptr_mi : g_rowptr_di;
    int n          = blockIdx.x ? N_MI : N_DI;

    __shared__ int warpsum[32];
    __shared__ int s_running;
    int tid = threadIdx.x, lane = tid & 31, wid = tid >> 5;
    if (tid == 0) s_running = 0;
    __syncthreads();

    for (int base = 0; base < n; base += 1024) {
        int i = base + tid;
        int v = (i < n) ? cnt[i] : 0;
        int x = v;
        #pragma unroll
        for (int off = 1; off < 32; off <<= 1) {
            int t = __shfl_up_sync(0xffffffffu, x, off);
            if (lane >= off) x += t;
        }
        if (lane == 31) warpsum[wid] = x;
        __syncthreads();
        if (wid == 0) {
            int w = warpsum[lane];
            #pragma unroll
            for (int off = 1; off < 32; off <<= 1) {
                int t = __shfl_up_sync(0xffffffffu, w, off);
                if (lane >= off) w += t;
            }
            warpsum[lane] = w;
        }
        __syncthreads();
        int incl = x + (wid ? warpsum[wid - 1] : 0);
        int run = s_running;
        if (i < n) rowptr[i] = run + incl - v;
        __syncthreads();
        if (tid == 1023) s_running = run + warpsum[31];
        __syncthreads();
    }
    if (threadIdx.x == 0) rowptr[n] = s_running;
}

__global__ void fill_edges(const int* __restrict__ src, const int* __restrict__ dst, int e) {
    int i = blockIdx.x * blockDim.x + threadIdx.x;
    if (i < e) {
        int s = src[i], d = dst[i];
        int pd = g_rowptr_di[d] + atomicAdd(&g_cnt_di[d], 1);
        g_col_di[pd] = s;
        int pm = g_rowptr_mi[s] + atomicAdd(&g_cnt_mi[s], 1);
        g_col_mi[pm] = d;
    }
}

// ---------------- mean aggregation: one warp per destination row ----------------
template <int D>
__global__ void agg_mean(const float* __restrict__ x, const int* __restrict__ rowptr,
                         const int* __restrict__ col, float* __restrict__ out, int n) {
    int warp = (blockIdx.x * blockDim.x + threadIdx.x) >> 5;
    int lane = threadIdx.x & 31;
    if (warp >= n) return;
    int s = rowptr[warp], e = rowptr[warp + 1];
    float acc[D / 32];
    #pragma unroll
    for (int j = 0; j < D / 32; ++j) acc[j] = 0.f;
    for (int i = s; i < e; ++i) {
        int srcid = col[i];
        const float* xr = x + (size_t)srcid * D;
        #pragma unroll
        for (int j = 0; j < D / 32; ++j) acc[j] += __ldg(xr + lane + 32 * j);
    }
    float inv = 1.f / fmaxf((float)(e - s), 1.f);
    float* o = out + (size_t)warp * D;
    #pragma unroll
    for (int j = 0; j < D / 32; ++j) o[lane + 32 * j] = acc[j] * inv;
}

// ---------------- tf32 tensor-core GEMM ----------------
// C[M,N] = A0[M,K]@B0[N,K]^T (+ A1@B1^T) + bias (+ addend), optional relu
__device__ __forceinline__ unsigned f2tf32(float x) {
    unsigned u;
    asm("cvt.rna.tf32.f32 %0, %1;" : "=r"(u) : "f"(x));
    return u;
}

__device__ __forceinline__ void mma_tf32(float* c, const unsigned* a, const unsigned* b) {
    asm volatile(
        "mma.sync.aligned.m16n8k8.row.col.f32.tf32.tf32.f32 "
        "{%0,%1,%2,%3}, {%4,%5,%6,%7}, {%8,%9}, {%0,%1,%2,%3};"
        : "+f"(c[0]), "+f"(c[1]), "+f"(c[2]), "+f"(c[3])
        : "r"(a[0]), "r"(a[1]), "r"(a[2]), "r"(a[3]), "r"(b[0]), "r"(b[1]));
}

template <int BN>
__global__ void __launch_bounds__(256, 2) tf32_gemm(
    const float* __restrict__ A0, const float* __restrict__ B0,
    const float* __restrict__ A1, const float* __restrict__ B1,
    const float* __restrict__ bias, const float* __restrict__ addend,
    float* __restrict__ C, int M, int N, int K, int relu) {

    constexpr int BM = 128, BK = 32;
    constexpr int WN = BN / 4;      // warp n-extent (2x4 warp grid)
    constexpr int NT = WN / 8;      // n8 tiles per warp
    constexpr int NB = BN / 32;     // B float4 loads per thread

    __shared__ float As[BM][BK + 4];
    __shared__ float Bs[BN][BK + 4];

    const int tid = threadIdx.x;
    const int lane = tid & 31, wid = tid >> 5;
    const int wm = wid & 1, wn = wid >> 1;
    const int group = lane >> 2, tig = lane & 3;
    const int m0 = blockIdx.y * BM, n0 = blockIdx.x * BN;

    float acc[4][NT][4];
    #pragma unroll
    for (int i = 0; i < 4; ++i)
        #pragma unroll
        for (int j = 0; j < NT; ++j)
            #pragma unroll
            for (int q = 0; q < 4; ++q) acc[i][j][q] = 0.f;

    const int ktiles = K / BK;
    const int total = (A1 ? 2 : 1) * ktiles;

    float4 ra[4];
    float4 rb[NB];

    auto load_tile = [&](int t) {
        const int p = (t >= ktiles) ? 1 : 0;
        const int kk0 = (t - p * ktiles) * BK;
        const float* Ap = p ? A1 : A0;
        const float* Bp = p ? B1 : B0;
        #pragma unroll
        for (int it = 0; it < 4; ++it) {
            int idx = it * 256 + tid, r = idx >> 3, c4 = (idx & 7) << 2;
            ra[it] = (m0 + r < M)
                ? *(const float4*)(Ap + (size_t)(m0 + r) * K + kk0 + c4)
                : make_float4(0.f, 0.f, 0.f, 0.f);
        }
        #pragma unroll
        for (int it = 0; it < NB; ++it) {
            int idx = it * 256 + tid, r = idx >> 3, c4 = (idx & 7) << 2;
            rb[it] = *(const float4*)(Bp + (size_t)(n0 + r) * K + kk0 + c4);
        }
    };

    load_tile(0);

    for (int t = 0; t < total; ++t) {
        __syncthreads();   // previous compute done before overwriting smem
        #pragma unroll
        for (int it = 0; it < 4; ++it) {
            int idx = it * 256 + tid, r = idx >> 3, c4 = (idx & 7) << 2;
            As[r][c4 + 0] = __uint_as_float(f2tf32(ra[it].x));
            As[r][c4 + 1] = __uint_as_float(f2tf32(ra[it].y));
            As[r][c4 + 2] = __uint_as_float(f2tf32(ra[it].z));
            As[r][c4 + 3] = __uint_as_float(f2tf32(ra[it].w));
        }
        #pragma unroll
        for (int it = 0; it < NB; ++it) {
            int idx = it * 256 + tid, r = idx >> 3, c4 = (idx & 7) << 2;
            Bs[r][c4 + 0] = __uint_as_float(f2tf32(rb[it].x));
            Bs[r][c4 + 1] = __uint_as_float(f2tf32(rb[it].y));
            Bs[r][c4 + 2] = __uint_as_float(f2tf32(rb[it].z));
            Bs[r][c4 + 3] = __uint_as_float(f2tf32(rb[it].w));
        }
        __syncthreads();
        if (t + 1 < total) load_tile(t + 1);   // LDGs in flight during compute

        #pragma unroll
        for (int ks = 0; ks < 4; ++ks) {
            const int kk = ks * 8;
            unsigned af[4][4];
            #pragma unroll
            for (int i = 0; i < 4; ++i) {
                int r = wm * 64 + i * 16 + group;
                af[i][0] = __float_as_uint(As[r][kk + tig]);
                af[i][1] = __float_as_uint(As[r + 8][kk + tig]);
                af[i][2] = __float_as_uint(As[r][kk + tig + 4]);
                af[i][3] = __float_as_uint(As[r + 8][kk + tig + 4]);
            }
            unsigned bf[NT][2];
            #pragma unroll
            for (int j = 0; j < NT; ++j) {
                int nl = wn * WN + j * 8 + group;
                bf[j][0] = __float_as_uint(Bs[nl][kk + tig]);
                bf[j][1] = __float_as_uint(Bs[nl][kk + tig + 4]);
            }
            #pragma unroll
            for (int i = 0; i < 4; ++i)
                #pragma unroll
                for (int j = 0; j < NT; ++j)
                    mma_tf32(acc[i][j], af[i], bf[j]);
        }
    }

    // epilogue
    #pragma unroll
    for (int i = 0; i < 4; ++i) {
        int row = m0 + wm * 64 + i * 16 + group;
        #pragma unroll
        for (int j = 0; j < NT; ++j) {
            int col = n0 + wn * WN + j * 8 + 2 * tig;
            float b0 = __ldg(bias + col), b1 = __ldg(bias + col + 1);
            if (row < M) {
                float v0 = acc[i][j][0] + b0, v1 = acc[i][j][1] + b1;
                if (addend) {
                    v0 += addend[(size_t)row * N + col];
                    v1 += addend[(size_t)row * N + col + 1];
                }
                if (relu) { v0 = fmaxf(v0, 0.f); v1 = fmaxf(v1, 0.f); }
                *(float2*)(C + (size_t)row * N + col) = make_float2(v0, v1);
            }
            int row2 = row + 8;
            if (row2 < M) {
                float v0 = acc[i][j][2] + b0, v1 = acc[i][j][3] + b1;
                if (addend) {
                    v0 += addend[(size_t)row2 * N + col];
                    v1 += addend[(size_t)row2 * N + col + 1];
                }
                if (relu) { v0 = fmaxf(v0, 0.f); v1 = fmaxf(v1, 0.f); }
                *(float2*)(C + (size_t)row2 * N + col) = make_float2(v0, v1);
            }
        }
    }
}

static void launch_gemm(const float* A0, const float* B0,
                        const float* A1, const float* B1,
                        const float* bias, const float* addend,
                        float* C, int M, int N, int K, int relu) {
    if (N % 128 == 0)
        tf32_gemm<128><<<dim3(N / 128, (M + 127) / 128), 256>>>(
            A0, B0, A1, B1, bias, addend, C, M, N, K, relu);
    else
        tf32_gemm<64><<<dim3(N / 64, (M + 127) / 128), 256>>>(
            A0, B0, A1, B1, bias, addend, C, M, N, K, relu);
}

// ---------------- classifier ----------------
__global__ void dot64(const float* __restrict__ hmi, const float* __restrict__ hdi,
                      const int* __restrict__ lsrc, const int* __restrict__ ldst,
                      float* __restrict__ out, int L) {
    int warp = (blockIdx.x * blockDim.x + threadIdx.x) >> 5;
    int lane = threadIdx.x & 31;
    if (warp >= L) return;
    const float2* a = (const float2*)(hmi + (size_t)lsrc[warp] * 64);
    const float2* b = (const float2*)(hdi + (size_t)ldst[warp] * 64);
    float2 av = a[lane], bv = b[lane];
    float p = av.x * bv.x + av.y * bv.y;
    #pragma unroll
    for (int off = 16; off; off >>= 1) p += __shfl_down_sync(0xffffffffu, p, off);
    if (lane == 0) out[warp] = p;
}

// ---------------- host orchestration ----------------
extern "C" void kernel_launch(void* const* d_in, const int* in_sizes, int n_in,
                              void* d_out, int out_size) {
    const float* x_mi   = (const float*)d_in[0];
    const float* x_di   = (const float*)d_in[1];
    const float* W_mi   = (const float*)d_in[2];
    const float* b_mi   = (const float*)d_in[3];
    const float* W_di   = (const float*)d_in[4];
    const float* b_di   = (const float*)d_in[5];
    const float* emb_mi = (const float*)d_in[6];
    const float* emb_di = (const float*)d_in[7];
    const float *Wl[3][2], *bl[3][2], *Wr[3][2];
    for (int i = 0; i < 3; ++i)
        for (int r = 0; r < 2; ++r) {
            int base = 8 + i * 6 + r * 3;
            Wl[i][r] = (const float*)d_in[base];
            bl[i][r] = (const float*)d_in[base + 1];
            Wr[i][r] = (const float*)d_in[base + 2];
        }
    const int* edge_src  = (const int*)d_in[26];
    const int* edge_dst  = (const int*)d_in[27];
    const int* label_src = (const int*)d_in[28];
    const int* label_dst = (const int*)d_in[29];
    float* out = (float*)d_out;

    float *hA_mi, *hB_mi, *hA_di, *hB_di, *mean_mi, *mean_di;
    int *rp_di, *rp_mi, *col_di, *col_mi, *cnt_di, *cnt_mi;
    cudaGetSymbolAddress((void**)&hA_mi, g_hA_mi);
    cudaGetSymbolAddress((void**)&hB_mi, g_hB_mi);
    cudaGetSymbolAddress((void**)&hA_di, g_hA_di);
    cudaGetSymbolAddress((void**)&hB_di, g_hB_di);
    cudaGetSymbolAddress((void**)&mean_mi, g_mean_mi);
    cudaGetSymbolAddress((void**)&mean_di, g_mean_di);
    cudaGetSymbolAddress((void**)&rp_di, g_rowptr_di);
    cudaGetSymbolAddress((void**)&rp_mi, g_rowptr_mi);
    cudaGetSymbolAddress((void**)&col_di, g_col_di);
    cudaGetSymbolAddress((void**)&col_mi, g_col_mi);
    cudaGetSymbolAddress((void**)&cnt_di, g_cnt_di);
    cudaGetSymbolAddress((void**)&cnt_mi, g_cnt_mi);

    const int EB = (N_E + 255) / 256;

    // ---- CSR build ----
    cudaMemsetAsync(cnt_di, 0, N_DI * sizeof(int));
    cudaMemsetAsync(cnt_mi, 0, N_MI * sizeof(int));
    count_edges<<<EB, 256>>>(edge_src, edge_dst, N_E);
    scan2<<<2, 1024>>>();
    cudaMemsetAsync(cnt_di, 0, N_DI * sizeof(int));
    cudaMemsetAsync(cnt_mi, 0, N_MI * sizeof(int));
    fill_edges<<<EB, 256>>>(edge_src, edge_dst, N_E);

    // ---- input projections: h = x @ W^T + b + emb ----
    launch_gemm(x_mi, W_mi, nullptr, nullptr, b_mi, emb_mi, hA_mi, N_MI, H_C, F_MI_C, 0);
    launch_gemm(x_di, W_di, nullptr, nullptr, b_di, emb_di, hA_di, N_DI, H_C, F_DI_C, 0);

    const int AG_DI = (N_DI + 7) / 8;
    const int AG_MI = (N_MI + 7) / 8;

    // ---- Layer 1: 128 -> 256, relu ----
    agg_mean<128><<<AG_DI, 256>>>(hA_mi, rp_di, col_di, mean_di, N_DI);
    agg_mean<128><<<AG_MI, 256>>>(hA_di, rp_mi, col_mi, mean_mi, N_MI);
    launch_gemm(mean_di, Wl[0][0], hA_di, Wr[0][0], bl[0][0], nullptr, hB_di, N_DI, 256, 128, 1);
    launch_gemm(mean_mi, Wl[0][1], hA_mi, Wr[0][1], bl[0][1], nullptr, hB_mi, N_MI, 256, 128, 1);

    // ---- Layer 2: 256 -> 128, relu ----
    agg_mean<256><<<AG_DI, 256>>>(hB_mi, rp_di, col_di, mean_di, N_DI);
    agg_mean<256><<<AG_MI, 256>>>(hB_di, rp_mi, col_mi, mean_mi, N_MI);
    launch_gemm(mean_di, Wl[1][0], hB_di, Wr[1][0], bl[1][0], nullptr, hA_di, N_DI, 128, 256, 1);
    launch_gemm(mean_mi, Wl[1][1], hB_mi, Wr[1][1], bl[1][1], nullptr, hA_mi, N_MI, 128, 256, 1);

    // ---- Layer 3: 128 -> 64, no relu ----
    agg_mean<128><<<AG_DI, 256>>>(hA_mi, rp_di, col_di, mean_di, N_DI);
    agg_mean<128><<<AG_MI, 256>>>(hA_di, rp_mi, col_mi, mean_mi, N_MI);
    launch_gemm(mean_di, Wl[2][0], hA_di, Wr[2][0], bl[2][0], nullptr, hB_di, N_DI, 64, 128, 0);
    launch_gemm(mean_mi, Wl[2][1], hA_mi, Wr[2][1], bl[2][1], nullptr, hB_mi, N_MI, 64, 128, 0);

    // ---- classifier ----
    dot64<<<(N_L + 7) / 8, 256>>>(hB_mi, hB_di, label_src, label_dst, out, N_L);
}